// round 1
// baseline (speedup 1.0000x reference)
#include <cuda_runtime.h>
#include <math.h>

#define HEADS   8
#define NBUCK   64
#define BSZ     64
#define DH      128
#define DMODEL  1024
#define TLEN    4096
#define NB      2
#define BH      16          // NB*HEADS
#define NROWS   8192        // NB*TLEN
#define QKVC    3072
#define TEMP_   0.75f
#define EPS_    1e-6f
#define SCALE_  0.03125f    // 1024^-0.5

// ------------------------- device scratch (no allocs allowed) ----------------
__device__ float g_qkv[(size_t)NROWS * QKVC];     // ~100.7 MB
__device__ float g_sx[BH * NBUCK * 256];
__device__ int   g_idx[BH * NBUCK];
__device__ float g_val[BH * NBUCK];
__device__ float g_ao[(size_t)NROWS * DMODEL];    // ~33.6 MB

// ------------------------- generic fp32 SGEMM --------------------------------
// C[M,N] = A[M,K] @ B[K,N] (+bias per column). Row-major. M,N %128==0, K%16==0.
__global__ void __launch_bounds__(256) sgemm128(
    const float* __restrict__ A, const float* __restrict__ Bm,
    const float* __restrict__ bias, float* __restrict__ C,
    int M, int N, int K)
{
    __shared__ float As[16][132];   // A tile transposed: As[k][row]
    __shared__ float Bs[16][132];   // B tile: Bs[k][col]

    const int tid  = threadIdx.x;
    const int row0 = blockIdx.y * 128;
    const int col0 = blockIdx.x * 128;
    const int tx   = tid & 15, ty = tid >> 4;

    // A-tile loads: 128 rows x 16 cols = 512 float4, 2 per thread
    const int ar = tid >> 2;             // 0..63 (and +64)
    const int ac = (tid & 3) * 4;        // 0,4,8,12
    // B-tile loads: 16 rows x 128 cols = 512 float4, 2 per thread
    const int br = tid >> 5;             // 0..7 (and +8)
    const int bc = (tid & 31) * 4;       // 0..124

    float acc[8][8];
    #pragma unroll
    for (int i = 0; i < 8; i++)
        #pragma unroll
        for (int j = 0; j < 8; j++) acc[i][j] = 0.f;

    for (int kt = 0; kt < K; kt += 16) {
        float4 av0 = *(const float4*)&A[(size_t)(row0 + ar)      * K + kt + ac];
        float4 av1 = *(const float4*)&A[(size_t)(row0 + ar + 64) * K + kt + ac];
        float4 bv0 = *(const float4*)&Bm[(size_t)(kt + br)     * N + col0 + bc];
        float4 bv1 = *(const float4*)&Bm[(size_t)(kt + br + 8) * N + col0 + bc];

        As[ac + 0][ar] = av0.x; As[ac + 1][ar] = av0.y;
        As[ac + 2][ar] = av0.z; As[ac + 3][ar] = av0.w;
        As[ac + 0][ar + 64] = av1.x; As[ac + 1][ar + 64] = av1.y;
        As[ac + 2][ar + 64] = av1.z; As[ac + 3][ar + 64] = av1.w;
        *(float4*)&Bs[br][bc]     = bv0;
        *(float4*)&Bs[br + 8][bc] = bv1;
        __syncthreads();

        #pragma unroll
        for (int kk = 0; kk < 16; kk++) {
            float4 a0 = *(const float4*)&As[kk][ty * 4];
            float4 a1 = *(const float4*)&As[kk][64 + ty * 4];
            float4 b0 = *(const float4*)&Bs[kk][tx * 4];
            float4 b1 = *(const float4*)&Bs[kk][64 + tx * 4];
            float a[8] = {a0.x, a0.y, a0.z, a0.w, a1.x, a1.y, a1.z, a1.w};
            float b[8] = {b0.x, b0.y, b0.z, b0.w, b1.x, b1.y, b1.z, b1.w};
            #pragma unroll
            for (int i = 0; i < 8; i++)
                #pragma unroll
                for (int j = 0; j < 8; j++)
                    acc[i][j] += a[i] * b[j];
        }
        __syncthreads();
    }

    float4 blo = make_float4(0.f, 0.f, 0.f, 0.f), bhi = blo;
    if (bias) {
        blo = *(const float4*)&bias[col0 + tx * 4];
        bhi = *(const float4*)&bias[col0 + 64 + tx * 4];
    }
    #pragma unroll
    for (int ii = 0; ii < 8; ii++) {
        int rrow = row0 + ((ii < 4) ? (ty * 4 + ii) : (64 + ty * 4 + ii - 4));
        float4 lo = make_float4(acc[ii][0] + blo.x, acc[ii][1] + blo.y,
                                acc[ii][2] + blo.z, acc[ii][3] + blo.w);
        float4 hi = make_float4(acc[ii][4] + bhi.x, acc[ii][5] + bhi.y,
                                acc[ii][6] + bhi.z, acc[ii][7] + bhi.w);
        *(float4*)&C[(size_t)rrow * N + col0 + tx * 4]      = lo;
        *(float4*)&C[(size_t)rrow * N + col0 + 64 + tx * 4] = hi;
    }
}

// ------------------------- bucket sums: sx = [sum_q, sum_k] ------------------
__global__ void __launch_bounds__(256) bucket_sum_kernel(
    const float* __restrict__ qkv, float* __restrict__ sx)
{
    const int blk = blockIdx.x;              // bh*64 + u
    const int bh = blk >> 6, u = blk & 63;
    const int bi = bh >> 3, hi = bh & 7;
    const int e = threadIdx.x;               // 0..255
    const int col = (e < 128) ? (hi * DH + e) : (DMODEL + hi * DH + (e - 128));
    const float* base = qkv + ((size_t)(bi * TLEN + u * BSZ)) * QKVC + col;
    float a = 0.f;
    #pragma unroll 8
    for (int i = 0; i < BSZ; i++) a += base[(size_t)i * QKVC];
    sx[(size_t)blk * 256 + e] = a;
}

// ---------------- SortNet + Gumbel-Sinkhorn + top-1 --------------------------
__global__ void __launch_bounds__(256) sortnet_sinkhorn_kernel(
    const float* __restrict__ sx, const float* __restrict__ sw,
    const float* __restrict__ gum, int* __restrict__ idx_out,
    float* __restrict__ val_out)
{
    __shared__ float r[64][65];
    const int bh  = blockIdx.x;
    const int hi  = bh & 7;
    const int tid = threadIdx.x;
    const int u   = tid >> 2;                // 0..63
    const int vq  = (tid & 3) * 16;          // 0,16,32,48

    // R[u][vq..vq+15] = leaky_relu( sx[bh,u,:] @ W[hi][:, vq..] )
    float acc[16];
    #pragma unroll
    for (int v = 0; v < 16; v++) acc[v] = 0.f;
    const float* sxrow = sx + ((size_t)(bh * 64 + u)) * 256;
    const float* W = sw + (size_t)hi * 256 * 64 + vq;
    for (int e = 0; e < 256; e++) {
        float s = sxrow[e];
        #pragma unroll
        for (int v = 0; v < 16; v++) acc[v] += s * W[(size_t)e * 64 + v];
    }
    #pragma unroll
    for (int v = 0; v < 16; v++) {
        float R = acc[v];
        R = (R > 0.f) ? R : 0.01f * R;                    // leaky_relu(0.01)
        float gu = gum[((size_t)(bh * 64 + u)) * 64 + vq + v];
        float g  = -logf(-logf(gu + EPS_) + EPS_);
        r[u][vq + v] = (logf(fmaxf(R + EPS_, EPS_)) + g) / TEMP_;
    }
    __syncthreads();

    for (int it = 0; it < 5; it++) {
        if (tid < 64) {   // subtract row logsumexp (axis=2)
            float m = -1e30f;
            for (int v = 0; v < 64; v++) m = fmaxf(m, r[tid][v]);
            float s = 0.f;
            for (int v = 0; v < 64; v++) s += __expf(r[tid][v] - m);
            float lse = m + logf(s);
            for (int v = 0; v < 64; v++) r[tid][v] -= lse;
        }
        __syncthreads();
        if (tid < 64) {   // subtract col logsumexp (axis=1)
            float m = -1e30f;
            for (int i = 0; i < 64; i++) m = fmaxf(m, r[i][tid]);
            float s = 0.f;
            for (int i = 0; i < 64; i++) s += __expf(r[i][tid] - m);
            float lse = m + logf(s);
            for (int i = 0; i < 64; i++) r[i][tid] -= lse;
        }
        __syncthreads();
    }

    if (tid < 64) {   // top-1 along v (first max, like jnp.argmax)
        int best = 0; float bm = r[tid][0];
        for (int v = 1; v < 64; v++) {
            float rv = r[tid][v];
            if (rv > bm) { bm = rv; best = v; }
        }
        idx_out[bh * 64 + tid] = best;
        val_out[bh * 64 + tid] = __expf(bm);
    }
}

// ------------------------- bucketed attention --------------------------------
// One CTA per (bh, bucket). q:64x128, k2/v2:128x128 (first 64 rows = scaled
// gather from src bucket, next 64 = local bucket). smem stride 132 floats
// (=33*16B) -> conflict-free scalar AND float4 column access.
#define ATT_SMEM_FLOATS ((64 + 128) * 132)
#define ATT_SMEM_BYTES  (ATT_SMEM_FLOATS * 4)

__global__ void __launch_bounds__(256, 2) attn_kernel(
    const float* __restrict__ qkv, const int* __restrict__ idxv,
    const float* __restrict__ valv, float* __restrict__ ao)
{
    extern __shared__ float sm[];
    float* qs = sm;               // 64 x 132 : q, then P (reused)
    float* kv = sm + 64 * 132;    // 128 x 132 : k2, then v2 (reused)

    const int blk = blockIdx.x;
    const int bh = blk >> 6, u = blk & 63;
    const int bi = bh >> 3, hi = bh & 7;
    const int tid = threadIdx.x;
    const int tx = tid & 31, ty = tid >> 5;

    const int   src = idxv[blk];
    const float pv  = valv[blk];

    const size_t rowq = (size_t)(bi * TLEN + u * BSZ);
    const size_t rows = (size_t)(bi * TLEN + src * BSZ);
    const int colq = hi * DH;

    for (int n = tid; n < 64 * 128; n += 256) {
        int i = n >> 7, dd = n & 127;
        qs[i * 132 + dd] = qkv[(rowq + i) * QKVC + colq + dd];
    }
    for (int n = tid; n < 128 * 128; n += 256) {
        int j = n >> 7, dd = n & 127;
        float xv;
        if (j < 64) xv = pv * qkv[(rows + j) * QKVC + DMODEL + colq + dd];
        else        xv =      qkv[(rowq + j - 64) * QKVC + DMODEL + colq + dd];
        kv[j * 132 + dd] = xv;
    }
    __syncthreads();

    // GEMM1: s[i][j] = q[i,:] . k2[j,:]   (i = ty+8*ii, j = tx+32*jj)
    float acc[8][4];
    #pragma unroll
    for (int a = 0; a < 8; a++)
        #pragma unroll
        for (int b = 0; b < 4; b++) acc[a][b] = 0.f;

    for (int dd = 0; dd < 128; dd += 4) {
        float4 bq[4];
        #pragma unroll
        for (int jj = 0; jj < 4; jj++)
            bq[jj] = *(const float4*)&kv[(tx + 32 * jj) * 132 + dd];
        #pragma unroll
        for (int ii = 0; ii < 8; ii++) {
            float4 aq = *(const float4*)&qs[(ty + 8 * ii) * 132 + dd];
            #pragma unroll
            for (int jj = 0; jj < 4; jj++)
                acc[ii][jj] += aq.x * bq[jj].x + aq.y * bq[jj].y
                             + aq.z * bq[jj].z + aq.w * bq[jj].w;
        }
    }

    // softmax over j (each row i lives entirely in one warp)
    float p[8][4];
    #pragma unroll
    for (int ii = 0; ii < 8; ii++) {
        float m = -1e30f;
        #pragma unroll
        for (int jj = 0; jj < 4; jj++) {
            acc[ii][jj] *= SCALE_;
            m = fmaxf(m, acc[ii][jj]);
        }
        #pragma unroll
        for (int off = 16; off > 0; off >>= 1)
            m = fmaxf(m, __shfl_xor_sync(0xffffffffu, m, off));
        float s = 0.f;
        #pragma unroll
        for (int jj = 0; jj < 4; jj++) {
            p[ii][jj] = __expf(acc[ii][jj] - m);
            s += p[ii][jj];
        }
        #pragma unroll
        for (int off = 16; off > 0; off >>= 1)
            s += __shfl_xor_sync(0xffffffffu, s, off);
        float inv = 1.f / s;
        #pragma unroll
        for (int jj = 0; jj < 4; jj++) p[ii][jj] *= inv;
    }
    __syncthreads();   // everyone done reading qs/kv

    // P -> qs, v2 -> kv
    #pragma unroll
    for (int ii = 0; ii < 8; ii++)
        #pragma unroll
        for (int jj = 0; jj < 4; jj++)
            qs[(ty + 8 * ii) * 132 + tx + 32 * jj] = p[ii][jj];

    for (int n = tid; n < 128 * 128; n += 256) {
        int j = n >> 7, dd = n & 127;
        float xv;
        if (j < 64) xv = pv * qkv[(rows + j) * QKVC + 2 * DMODEL + colq + dd];
        else        xv =      qkv[(rowq + j - 64) * QKVC + 2 * DMODEL + colq + dd];
        kv[j * 132 + dd] = xv;
    }
    __syncthreads();

    // GEMM2: out[i][e] = sum_j P[i][j] * v2[j][e]   (e = tx+32*ee)
    float acc2[8][4];
    #pragma unroll
    for (int a = 0; a < 8; a++)
        #pragma unroll
        for (int b = 0; b < 4; b++) acc2[a][b] = 0.f;

    for (int j = 0; j < 128; j += 4) {
        float bvv[4][4];
        #pragma unroll
        for (int jx = 0; jx < 4; jx++)
            #pragma unroll
            for (int ee = 0; ee < 4; ee++)
                bvv[jx][ee] = kv[(j + jx) * 132 + tx + 32 * ee];
        #pragma unroll
        for (int ii = 0; ii < 8; ii++) {
            float4 av = *(const float4*)&qs[(ty + 8 * ii) * 132 + j];
            #pragma unroll
            for (int ee = 0; ee < 4; ee++)
                acc2[ii][ee] += av.x * bvv[0][ee] + av.y * bvv[1][ee]
                              + av.z * bvv[2][ee] + av.w * bvv[3][ee];
        }
    }

    #pragma unroll
    for (int ii = 0; ii < 8; ii++) {
        const size_t row = rowq + (ty + 8 * ii);
        #pragma unroll
        for (int ee = 0; ee < 4; ee++)
            ao[row * DMODEL + colq + tx + 32 * ee] = acc2[ii][ee];
    }
}

// ------------------------- launcher ------------------------------------------
extern "C" void kernel_launch(void* const* d_in, const int* in_sizes, int n_in,
                              void* d_out, int out_size)
{
    const float* x      = (const float*)d_in[0];
    const float* gumbel = (const float*)d_in[1];
    const float* w_qkv  = (const float*)d_in[2];
    const float* sort_w = (const float*)d_in[3];
    const float* w_out  = (const float*)d_in[4];
    const float* b_out  = (const float*)d_in[5];
    float* out = (float*)d_out;

    float *qkv, *sx, *val, *ao; int* idx;
    cudaGetSymbolAddress((void**)&qkv, g_qkv);
    cudaGetSymbolAddress((void**)&sx,  g_sx);
    cudaGetSymbolAddress((void**)&idx, g_idx);
    cudaGetSymbolAddress((void**)&val, g_val);
    cudaGetSymbolAddress((void**)&ao,  g_ao);

    // 1) qkv = x @ w_qkv
    sgemm128<<<dim3(QKVC / 128, NROWS / 128), 256>>>(
        x, w_qkv, nullptr, qkv, NROWS, QKVC, DMODEL);

    // 2) bucket sums for SortNet
    bucket_sum_kernel<<<BH * NBUCK, 256>>>(qkv, sx);

    // 3) SortNet + gumbel-sinkhorn + top-1
    sortnet_sinkhorn_kernel<<<BH, 256>>>(sx, sort_w, gumbel, idx, val);

    // 4) bucketed attention with fused top-1 permute gather
    cudaFuncSetAttribute(attn_kernel,
                         cudaFuncAttributeMaxDynamicSharedMemorySize,
                         ATT_SMEM_BYTES);
    attn_kernel<<<BH * NBUCK, 256, ATT_SMEM_BYTES>>>(qkv, idx, val, ao);

    // 5) out = ao @ w_out + b_out
    sgemm128<<<dim3(DMODEL / 128, NROWS / 128), 256>>>(
        ao, w_out, b_out, out, NROWS, DMODEL, DMODEL);
}

// round 7
// speedup vs baseline: 2.0861x; 2.0861x over previous
#include <cuda_runtime.h>
#include <cuda_bf16.h>
#include <math.h>
#include <stdint.h>

#define HEADS   8
#define NBUCK   64
#define BSZ     64
#define DH      128
#define DMODEL  1024
#define TLEN    4096
#define NB      2
#define BH      16          // NB*HEADS
#define NROWS   8192        // NB*TLEN
#define QKVC    3072
#define TEMP_   0.75f
#define EPS_    1e-6f
#define SCALE_  0.03125f    // 1024^-0.5

// ------------------------- device scratch (no allocs allowed) ----------------
__device__ float          g_qkv[(size_t)NROWS * QKVC];     // fp32 qkv, ~100.7MB
__device__ float          g_sx[BH * NBUCK * 256];
__device__ int            g_idx[BH * NBUCK];
__device__ float          g_val[BH * NBUCK];
__device__ __nv_bfloat16  g_x0[(size_t)NROWS * DMODEL];
__device__ __nv_bfloat16  g_x1[(size_t)NROWS * DMODEL];
__device__ __nv_bfloat16  g_wq0[(size_t)QKVC * DMODEL];    // w_qkv^T hi
__device__ __nv_bfloat16  g_wq1[(size_t)QKVC * DMODEL];
__device__ __nv_bfloat16  g_wo0[(size_t)DMODEL * DMODEL];  // w_out^T hi
__device__ __nv_bfloat16  g_wo1[(size_t)DMODEL * DMODEL];
__device__ __nv_bfloat16  g_ao0[(size_t)NROWS * DMODEL];   // attn out hi
__device__ __nv_bfloat16  g_ao1[(size_t)NROWS * DMODEL];   // attn out lo

// ------------------------- helpers -------------------------------------------
#define SWZ(o) ((uint32_t)(o) ^ ((((uint32_t)(o)) >> 3) & 0x70u))

__device__ __forceinline__ uint32_t s2u(const void* p) {
    uint32_t a;
    asm("{ .reg .u64 t; cvta.to.shared.u64 t, %1; cvt.u32.u64 %0, t; }" : "=r"(a) : "l"(p));
    return a;
}

__device__ __forceinline__ void cp16(uint32_t s, const void* g) {
    asm volatile("cp.async.cg.shared.global [%0], [%1], 16;\n" :: "r"(s), "l"(g));
}

__device__ __forceinline__ void ldm4(uint32_t addr, uint32_t* r) {
    asm volatile("ldmatrix.sync.aligned.m8n8.x4.shared.b16 {%0,%1,%2,%3}, [%4];"
                 : "=r"(r[0]), "=r"(r[1]), "=r"(r[2]), "=r"(r[3]) : "r"(addr));
}

__device__ __forceinline__ void mma16816(float* c, const uint32_t* a, const uint32_t* b) {
    asm volatile(
        "mma.sync.aligned.m16n8k16.row.col.f32.bf16.bf16.f32 "
        "{%0,%1,%2,%3}, {%4,%5,%6,%7}, {%8,%9}, {%0,%1,%2,%3};"
        : "+f"(c[0]), "+f"(c[1]), "+f"(c[2]), "+f"(c[3])
        : "r"(a[0]), "r"(a[1]), "r"(a[2]), "r"(a[3]), "r"(b[0]), "r"(b[1]));
}

// ------------------------- bf16x2 HMMA GEMM ----------------------------------
// C[M,N] = (A0+A1)[M,K] @ (B0+B1)^T, B0/B1 stored [N,K] (pre-transposed).
// A0B0 + A0B1 + A1B0 (3 MMA terms) ~= fp32 precision.
// 128x128 CTA tile, 8 warps (4m x 2n), warp tile 32x64, K-chunk 64,
// 3-stage cp.async pipeline, SW128-swizzled smem, ldmatrix fragments.
#define GSTAGE 65536
#define GEMM_SMEM (3 * GSTAGE)

__global__ void __launch_bounds__(256, 1) gemm_mma(
    const __nv_bfloat16* __restrict__ A0, const __nv_bfloat16* __restrict__ A1,
    const __nv_bfloat16* __restrict__ B0, const __nv_bfloat16* __restrict__ B1,
    const float* __restrict__ bias, float* __restrict__ C,
    int M, int N, int K)
{
    extern __shared__ char smem[];
    const uint32_t sbase = s2u(smem);

    const int tid = threadIdx.x, wid = tid >> 5, lid = tid & 31;
    const int col0 = blockIdx.x * 128, row0 = blockIdx.y * 128;
    const int wm = wid & 3;        // m block: rows wm*32
    const int wn = wid >> 2;       // n block: cols wn*64

    const int NK = K >> 6;

    // tile loader: 4 tiles (A0,A1,B0,B1) of 128 rows x 128B each, SW128
    auto load_chunk = [&](int s) {
        const int kt = s << 6;
        const uint32_t sb = sbase + (uint32_t)(s % 3) * GSTAGE;
        const __nv_bfloat16* pa0 = A0 + (size_t)row0 * K + kt;
        const __nv_bfloat16* pa1 = A1 + (size_t)row0 * K + kt;
        const __nv_bfloat16* pb0 = B0 + (size_t)col0 * K + kt;
        const __nv_bfloat16* pb1 = B1 + (size_t)col0 * K + kt;
        #pragma unroll
        for (int i = 0; i < 4; i++) {
            const int id = tid + i * 256;        // 0..1023
            const int r = id >> 3, c = id & 7;
            const uint32_t sw = SWZ(r * 128 + c * 16);
            const size_t go = (size_t)r * K + c * 8;
            cp16(sb + sw,           pa0 + go);
            cp16(sb + 16384u + sw,  pa1 + go);
            cp16(sb + 32768u + sw,  pb0 + go);
            cp16(sb + 49152u + sw,  pb1 + go);
        }
        asm volatile("cp.async.commit_group;" ::: "memory");
    };

    float acc[16][4];              // [mt*8 + nt][4], mt in 0..1, nt in 0..7
    #pragma unroll
    for (int i = 0; i < 16; i++)
        #pragma unroll
        for (int j = 0; j < 4; j++) acc[i][j] = 0.f;

    load_chunk(0);
    load_chunk(1);

    // per-lane ldmatrix row indices (fixed across chunks)
    const int arow[2] = { wm * 32 +  (lid & 15),           // mt=0 rows
                          wm * 32 + 16 + (lid & 15) };     // mt=1 rows
    const int ahalf = lid >> 4;                            // k-half select
    const int brow_base = wn * 64 + ((lid >> 4) << 3) + (lid & 7);
    const int bhalf = (lid >> 3) & 1;

    for (int s = 0; s < NK; s++) {
        if (s + 1 < NK) asm volatile("cp.async.wait_group 1;" ::: "memory");
        else            asm volatile("cp.async.wait_group 0;" ::: "memory");
        __syncthreads();

        if (s + 2 < NK) load_chunk(s + 2);

        const uint32_t sb = sbase + (uint32_t)(s % 3) * GSTAGE;
        const uint32_t SA0 = sb, SA1 = sb + 16384u;
        const uint32_t SB0 = sb + 32768u, SB1 = sb + 49152u;

        #pragma unroll
        for (int ks = 0; ks < 4; ks++) {
            uint32_t ah[2][4], al[2][4];
            #pragma unroll
            for (int mt = 0; mt < 2; mt++) {
                const int r = arow[mt];
                const uint32_t off = (uint32_t)r * 128u
                                   + (uint32_t)(((2 * ks + ahalf) ^ (r & 7)) * 16);
                ldm4(SA0 + off, ah[mt]);
                ldm4(SA1 + off, al[mt]);
            }
            uint32_t bh[8][2], bl[8][2];
            #pragma unroll
            for (int ng = 0; ng < 4; ng++) {
                const int r = brow_base + ng * 16;
                const uint32_t off = (uint32_t)r * 128u
                                   + (uint32_t)(((2 * ks + bhalf) ^ (r & 7)) * 16);
                uint32_t t[4];
                ldm4(SB0 + off, t);
                bh[2*ng][0] = t[0]; bh[2*ng][1] = t[1];
                bh[2*ng+1][0] = t[2]; bh[2*ng+1][1] = t[3];
                ldm4(SB1 + off, t);
                bl[2*ng][0] = t[0]; bl[2*ng][1] = t[1];
                bl[2*ng+1][0] = t[2]; bl[2*ng+1][1] = t[3];
            }
            // term 1: A_hi * B_hi
            #pragma unroll
            for (int mt = 0; mt < 2; mt++)
                #pragma unroll
                for (int nt = 0; nt < 8; nt++)
                    mma16816(acc[mt * 8 + nt], ah[mt], bh[nt]);
            // term 2: A_hi * B_lo
            #pragma unroll
            for (int mt = 0; mt < 2; mt++)
                #pragma unroll
                for (int nt = 0; nt < 8; nt++)
                    mma16816(acc[mt * 8 + nt], ah[mt], bl[nt]);
            // term 3: A_lo * B_hi
            #pragma unroll
            for (int mt = 0; mt < 2; mt++)
                #pragma unroll
                for (int nt = 0; nt < 8; nt++)
                    mma16816(acc[mt * 8 + nt], al[mt], bh[nt]);
        }
        __syncthreads();
    }

    // epilogue: write accumulators (+bias)
    #pragma unroll
    for (int mt = 0; mt < 2; mt++) {
        #pragma unroll
        for (int nt = 0; nt < 8; nt++) {
            const float* c = acc[mt * 8 + nt];
            const int r0 = row0 + wm * 32 + mt * 16 + (lid >> 2);
            const int cc = col0 + wn * 64 + nt * 8 + (lid & 3) * 2;
            float b0v = 0.f, b1v = 0.f;
            if (bias) { b0v = bias[cc]; b1v = bias[cc + 1]; }
            *(float2*)&C[(size_t)r0 * N + cc] =
                make_float2(c[0] + b0v, c[1] + b1v);
            *(float2*)&C[(size_t)(r0 + 8) * N + cc] =
                make_float2(c[2] + b0v, c[3] + b1v);
        }
    }
}

// ------------------------- fp32 -> bf16 hi/lo split --------------------------
__global__ void __launch_bounds__(256) split_kernel(
    const float* __restrict__ in, __nv_bfloat16* __restrict__ h,
    __nv_bfloat16* __restrict__ l, int n4)
{
    int i = blockIdx.x * blockDim.x + threadIdx.x;
    if (i >= n4) return;
    float4 v = ((const float4*)in)[i];
    float vs[4] = {v.x, v.y, v.z, v.w};
    #pragma unroll
    for (int j = 0; j < 4; j++) {
        __nv_bfloat16 hi = __float2bfloat16(vs[j]);
        __nv_bfloat16 lo = __float2bfloat16(vs[j] - __bfloat162float(hi));
        h[(size_t)i * 4 + j] = hi;
        l[(size_t)i * 4 + j] = lo;
    }
}

// -------------------- transpose + split: W[K,N] -> T0/T1 [N,K] ---------------
__global__ void __launch_bounds__(256) tsplit_kernel(
    const float* __restrict__ W, __nv_bfloat16* __restrict__ T0,
    __nv_bfloat16* __restrict__ T1, int K, int N)
{
    __shared__ float t[32][33];
    const int n0 = blockIdx.x * 32, k0 = blockIdx.y * 32;
    const int x = threadIdx.x & 31, y = threadIdx.x >> 5;   // 32 x 8
    #pragma unroll
    for (int j = 0; j < 32; j += 8)
        t[y + j][x] = W[(size_t)(k0 + y + j) * N + n0 + x];
    __syncthreads();
    #pragma unroll
    for (int j = 0; j < 32; j += 8) {
        float v = t[x][y + j];
        __nv_bfloat16 hi = __float2bfloat16(v);
        __nv_bfloat16 lo = __float2bfloat16(v - __bfloat162float(hi));
        size_t o = (size_t)(n0 + y + j) * K + k0 + x;
        T0[o] = hi; T1[o] = lo;
    }
}

// ------------------------- bucket sums: sx = [sum_q, sum_k] ------------------
__global__ void __launch_bounds__(256) bucket_sum_kernel(
    const float* __restrict__ qkv, float* __restrict__ sx)
{
    const int blk = blockIdx.x;              // bh*64 + u
    const int bh = blk >> 6, u = blk & 63;
    const int bi = bh >> 3, hi = bh & 7;
    const int e = threadIdx.x;               // 0..255
    const int col = (e < 128) ? (hi * DH + e) : (DMODEL + hi * DH + (e - 128));
    const float* base = qkv + ((size_t)(bi * TLEN + u * BSZ)) * QKVC + col;
    float a = 0.f;
    #pragma unroll 8
    for (int i = 0; i < BSZ; i++) a += base[(size_t)i * QKVC];
    sx[(size_t)blk * 256 + e] = a;
}

// ---------------- SortNet + Gumbel-Sinkhorn + top-1 --------------------------
__global__ void __launch_bounds__(256) sortnet_sinkhorn_kernel(
    const float* __restrict__ sx, const float* __restrict__ sw,
    const float* __restrict__ gum, int* __restrict__ idx_out,
    float* __restrict__ val_out)
{
    __shared__ float r[64][65];
    const int bh  = blockIdx.x;
    const int hi  = bh & 7;
    const int tid = threadIdx.x;
    const int u   = tid >> 2;                // 0..63
    const int vq  = (tid & 3) * 16;          // 0,16,32,48

    float acc[16];
    #pragma unroll
    for (int v = 0; v < 16; v++) acc[v] = 0.f;
    const float* sxrow = sx + ((size_t)(bh * 64 + u)) * 256;
    const float* W = sw + (size_t)hi * 256 * 64 + vq;
    for (int e = 0; e < 256; e++) {
        float s = sxrow[e];
        #pragma unroll
        for (int v = 0; v < 16; v++) acc[v] += s * W[(size_t)e * 64 + v];
    }
    #pragma unroll
    for (int v = 0; v < 16; v++) {
        float R = acc[v];
        R = (R > 0.f) ? R : 0.01f * R;
        float gu = gum[((size_t)(bh * 64 + u)) * 64 + vq + v];
        float g  = -logf(-logf(gu + EPS_) + EPS_);
        r[u][vq + v] = (logf(fmaxf(R + EPS_, EPS_)) + g) / TEMP_;
    }
    __syncthreads();

    for (int it = 0; it < 5; it++) {
        if (tid < 64) {
            float m = -1e30f;
            for (int v = 0; v < 64; v++) m = fmaxf(m, r[tid][v]);
            float s = 0.f;
            for (int v = 0; v < 64; v++) s += __expf(r[tid][v] - m);
            float lse = m + logf(s);
            for (int v = 0; v < 64; v++) r[tid][v] -= lse;
        }
        __syncthreads();
        if (tid < 64) {
            float m = -1e30f;
            for (int i = 0; i < 64; i++) m = fmaxf(m, r[i][tid]);
            float s = 0.f;
            for (int i = 0; i < 64; i++) s += __expf(r[i][tid] - m);
            float lse = m + logf(s);
            for (int i = 0; i < 64; i++) r[i][tid] -= lse;
        }
        __syncthreads();
    }

    if (tid < 64) {
        int best = 0; float bm = r[tid][0];
        for (int v = 1; v < 64; v++) {
            float rv = r[tid][v];
            if (rv > bm) { bm = rv; best = v; }
        }
        idx_out[bh * 64 + tid] = best;
        val_out[bh * 64 + tid] = __expf(bm);
    }
}

// ------------------------- bucketed attention --------------------------------
#define ATT_SMEM_FLOATS ((64 + 128) * 132)
#define ATT_SMEM_BYTES  (ATT_SMEM_FLOATS * 4)

__global__ void __launch_bounds__(256, 2) attn_kernel(
    const float* __restrict__ qkv, const int* __restrict__ idxv,
    const float* __restrict__ valv, __nv_bfloat16* __restrict__ ao0,
    __nv_bfloat16* __restrict__ ao1)
{
    extern __shared__ float sm[];
    float* qs = sm;               // 64 x 132 : q, then P (reused)
    float* kv = sm + 64 * 132;    // 128 x 132 : k2, then v2 (reused)

    const int blk = blockIdx.x;
    const int bh = blk >> 6, u = blk & 63;
    const int bi = bh >> 3, hi = bh & 7;
    const int tid = threadIdx.x;
    const int tx = tid & 31, ty = tid >> 5;

    const int   src = idxv[blk];
    const float pv  = valv[blk];

    const size_t rowq = (size_t)(bi * TLEN + u * BSZ);
    const size_t rows = (size_t)(bi * TLEN + src * BSZ);
    const int colq = hi * DH;

    for (int n = tid; n < 64 * 128; n += 256) {
        int i = n >> 7, dd = n & 127;
        qs[i * 132 + dd] = qkv[(rowq + i) * QKVC + colq + dd];
    }
    for (int n = tid; n < 128 * 128; n += 256) {
        int j = n >> 7, dd = n & 127;
        float xv;
        if (j < 64) xv = pv * qkv[(rows + j) * QKVC + DMODEL + colq + dd];
        else        xv =      qkv[(rowq + j - 64) * QKVC + DMODEL + colq + dd];
        kv[j * 132 + dd] = xv;
    }
    __syncthreads();

    float acc[8][4];
    #pragma unroll
    for (int a = 0; a < 8; a++)
        #pragma unroll
        for (int b = 0; b < 4; b++) acc[a][b] = 0.f;

    for (int dd = 0; dd < 128; dd += 4) {
        float4 bq[4];
        #pragma unroll
        for (int jj = 0; jj < 4; jj++)
            bq[jj] = *(const float4*)&kv[(tx + 32 * jj) * 132 + dd];
        #pragma unroll
        for (int ii = 0; ii < 8; ii++) {
            float4 aq = *(const float4*)&qs[(ty + 8 * ii) * 132 + dd];
            #pragma unroll
            for (int jj = 0; jj < 4; jj++)
                acc[ii][jj] += aq.x * bq[jj].x + aq.y * bq[jj].y
                             + aq.z * bq[jj].z + aq.w * bq[jj].w;
        }
    }

    float p[8][4];
    #pragma unroll
    for (int ii = 0; ii < 8; ii++) {
        float m = -1e30f;
        #pragma unroll
        for (int jj = 0; jj < 4; jj++) {
            acc[ii][jj] *= SCALE_;
            m = fmaxf(m, acc[ii][jj]);
        }
        #pragma unroll
        for (int off = 16; off > 0; off >>= 1)
            m = fmaxf(m, __shfl_xor_sync(0xffffffffu, m, off));
        float s = 0.f;
        #pragma unroll
        for (int jj = 0; jj < 4; jj++) {
            p[ii][jj] = __expf(acc[ii][jj] - m);
            s += p[ii][jj];
        }
        #pragma unroll
        for (int off = 16; off > 0; off >>= 1)
            s += __shfl_xor_sync(0xffffffffu, s, off);
        float inv = 1.f / s;
        #pragma unroll
        for (int jj = 0; jj < 4; jj++) p[ii][jj] *= inv;
    }
    __syncthreads();

    #pragma unroll
    for (int ii = 0; ii < 8; ii++)
        #pragma unroll
        for (int jj = 0; jj < 4; jj++)
            qs[(ty + 8 * ii) * 132 + tx + 32 * jj] = p[ii][jj];

    for (int n = tid; n < 128 * 128; n += 256) {
        int j = n >> 7, dd = n & 127;
        float xv;
        if (j < 64) xv = pv * qkv[(rows + j) * QKVC + 2 * DMODEL + colq + dd];
        else        xv =      qkv[(rowq + j - 64) * QKVC + 2 * DMODEL + colq + dd];
        kv[j * 132 + dd] = xv;
    }
    __syncthreads();

    float acc2[8][4];
    #pragma unroll
    for (int a = 0; a < 8; a++)
        #pragma unroll
        for (int b = 0; b < 4; b++) acc2[a][b] = 0.f;

    for (int j = 0; j < 128; j += 4) {
        float bvv[4][4];
        #pragma unroll
        for (int jx = 0; jx < 4; jx++)
            #pragma unroll
            for (int ee = 0; ee < 4; ee++)
                bvv[jx][ee] = kv[(j + jx) * 132 + tx + 32 * ee];
        #pragma unroll
        for (int ii = 0; ii < 8; ii++) {
            float4 av = *(const float4*)&qs[(ty + 8 * ii) * 132 + j];
            #pragma unroll
            for (int ee = 0; ee < 4; ee++)
                acc2[ii][ee] += av.x * bvv[0][ee] + av.y * bvv[1][ee]
                              + av.z * bvv[2][ee] + av.w * bvv[3][ee];
        }
    }

    #pragma unroll
    for (int ii = 0; ii < 8; ii++) {
        const size_t row = rowq + (ty + 8 * ii);
        #pragma unroll
        for (int ee = 0; ee < 4; ee++) {
            float v = acc2[ii][ee];
            __nv_bfloat16 hi2 = __float2bfloat16(v);
            __nv_bfloat16 lo2 = __float2bfloat16(v - __bfloat162float(hi2));
            size_t o = row * DMODEL + colq + tx + 32 * ee;
            ao0[o] = hi2; ao1[o] = lo2;
        }
    }
}

// ------------------------- launcher ------------------------------------------
extern "C" void kernel_launch(void* const* d_in, const int* in_sizes, int n_in,
                              void* d_out, int out_size)
{
    const float* x      = (const float*)d_in[0];
    const float* gumbel = (const float*)d_in[1];
    const float* w_qkv  = (const float*)d_in[2];
    const float* sort_w = (const float*)d_in[3];
    const float* w_out  = (const float*)d_in[4];
    const float* b_out  = (const float*)d_in[5];
    float* out = (float*)d_out;

    float *qkv, *sx, *val; int* idx;
    __nv_bfloat16 *x0, *x1, *wq0, *wq1, *wo0, *wo1, *ao0, *ao1;
    cudaGetSymbolAddress((void**)&qkv, g_qkv);
    cudaGetSymbolAddress((void**)&sx,  g_sx);
    cudaGetSymbolAddress((void**)&idx, g_idx);
    cudaGetSymbolAddress((void**)&val, g_val);
    cudaGetSymbolAddress((void**)&x0,  g_x0);
    cudaGetSymbolAddress((void**)&x1,  g_x1);
    cudaGetSymbolAddress((void**)&wq0, g_wq0);
    cudaGetSymbolAddress((void**)&wq1, g_wq1);
    cudaGetSymbolAddress((void**)&wo0, g_wo0);
    cudaGetSymbolAddress((void**)&wo1, g_wo1);
    cudaGetSymbolAddress((void**)&ao0, g_ao0);
    cudaGetSymbolAddress((void**)&ao1, g_ao1);

    cudaFuncSetAttribute(gemm_mma,
                         cudaFuncAttributeMaxDynamicSharedMemorySize, GEMM_SMEM);
    cudaFuncSetAttribute(attn_kernel,
                         cudaFuncAttributeMaxDynamicSharedMemorySize, ATT_SMEM_BYTES);

    // 0) split inputs to bf16 hi/lo
    {
        int n4 = NROWS * DMODEL / 4;
        split_kernel<<<(n4 + 255) / 256, 256>>>(x, x0, x1, n4);
    }
    tsplit_kernel<<<dim3(QKVC / 32, DMODEL / 32), 256>>>(w_qkv, wq0, wq1, DMODEL, QKVC);
    tsplit_kernel<<<dim3(DMODEL / 32, DMODEL / 32), 256>>>(w_out, wo0, wo1, DMODEL, DMODEL);

    // 1) qkv = x @ w_qkv  (HMMA bf16x2)
    gemm_mma<<<dim3(QKVC / 128, NROWS / 128), 256, GEMM_SMEM>>>(
        x0, x1, wq0, wq1, nullptr, qkv, NROWS, QKVC, DMODEL);

    // 2) bucket sums
    bucket_sum_kernel<<<BH * NBUCK, 256>>>(qkv, sx);

    // 3) SortNet + gumbel-sinkhorn + top-1
    sortnet_sinkhorn_kernel<<<BH, 256>>>(sx, sort_w, gumbel, idx, val);

    // 4) bucketed attention (fused top-1 gather; writes bf16 hi/lo)
    attn_kernel<<<BH * NBUCK, 256, ATT_SMEM_BYTES>>>(qkv, idx, val, ao0, ao1);

    // 5) out = ao @ w_out + b_out  (HMMA bf16x2)
    gemm_mma<<<dim3(DMODEL / 128, NROWS / 128), 256, GEMM_SMEM>>>(
        ao0, ao1, wo0, wo1, b_out, out, NROWS, DMODEL, DMODEL);
}

// round 9
// speedup vs baseline: 2.7426x; 1.3147x over previous
#include <cuda_runtime.h>
#include <cuda_bf16.h>
#include <cuda_fp16.h>
#include <math.h>
#include <stdint.h>

#define HEADS   8
#define NBUCK   64
#define BSZ     64
#define DH      128
#define DMODEL  1024
#define TLEN    4096
#define NB      2
#define BH      16          // NB*HEADS
#define NROWS   8192        // NB*TLEN
#define QKVC    3072
#define TEMP_   0.75f
#define EPS_    1e-6f
#define SCALE_  0.03125f    // 1024^-0.5

// ------------------------- device scratch (no allocs allowed) ----------------
__device__ float   g_qkv[(size_t)NROWS * QKVC];     // fp32 qkv, ~100.7MB
__device__ float   g_sx[BH * NBUCK * 256];
__device__ int     g_idx[BH * NBUCK];
__device__ float   g_val[BH * NBUCK];
__device__ __half  g_x0[(size_t)NROWS * DMODEL];    // x in fp16
__device__ __half  g_wq0[(size_t)QKVC * DMODEL];    // w_qkv^T hi
__device__ __half  g_wq1[(size_t)QKVC * DMODEL];    // w_qkv^T lo
__device__ __half  g_wo0[(size_t)DMODEL * DMODEL];  // w_out^T hi
__device__ __half  g_wo1[(size_t)DMODEL * DMODEL];  // w_out^T lo
__device__ __half  g_ao0[(size_t)NROWS * DMODEL];   // attn out fp16

// ------------------------- helpers -------------------------------------------
#define SWZ(o) ((uint32_t)(o) ^ ((((uint32_t)(o)) >> 3) & 0x70u))

__device__ __forceinline__ uint32_t s2u(const void* p) {
    uint32_t a;
    asm("{ .reg .u64 t; cvta.to.shared.u64 t, %1; cvt.u32.u64 %0, t; }" : "=r"(a) : "l"(p));
    return a;
}

__device__ __forceinline__ void cp16(uint32_t s, const void* g) {
    asm volatile("cp.async.cg.shared.global [%0], [%1], 16;\n" :: "r"(s), "l"(g));
}

__device__ __forceinline__ void ldm4(uint32_t addr, uint32_t* r) {
    asm volatile("ldmatrix.sync.aligned.m8n8.x4.shared.b16 {%0,%1,%2,%3}, [%4];"
                 : "=r"(r[0]), "=r"(r[1]), "=r"(r[2]), "=r"(r[3]) : "r"(addr));
}

__device__ __forceinline__ void mma16816(float* c, const uint32_t* a, const uint32_t* b) {
    asm volatile(
        "mma.sync.aligned.m16n8k16.row.col.f32.f16.f16.f32 "
        "{%0,%1,%2,%3}, {%4,%5,%6,%7}, {%8,%9}, {%0,%1,%2,%3};"
        : "+f"(c[0]), "+f"(c[1]), "+f"(c[2]), "+f"(c[3])
        : "r"(a[0]), "r"(a[1]), "r"(a[2]), "r"(a[3]), "r"(b[0]), "r"(b[1]));
}

// ------------------------- fp16 2-term HMMA GEMM -----------------------------
// C[M,N] = A0[M,K] @ (B0+B1)^T, B0/B1 stored [N,K] (pre-transposed fp16 hi/lo).
// Error ~2^-11 rms (dropped (A-A0)*B residual) -> final rel_err ~3e-4.
// 128x128 CTA tile, 8 warps (4m x 2n), warp tile 32x64, K-chunk 64,
// 2-stage cp.async double buffer (48KB/stage) -> 2 CTAs/SM.
#define GSTAGE 49152
#define GEMM_SMEM (2 * GSTAGE)

__global__ void __launch_bounds__(256, 2) gemm_mma(
    const __half* __restrict__ A0,
    const __half* __restrict__ B0, const __half* __restrict__ B1,
    const float* __restrict__ bias, float* __restrict__ C,
    int M, int N, int K)
{
    extern __shared__ char smem[];
    const uint32_t sbase = s2u(smem);

    const int tid = threadIdx.x, wid = tid >> 5, lid = tid & 31;
    const int col0 = blockIdx.x * 128, row0 = blockIdx.y * 128;
    const int wm = wid & 3;        // m block: rows wm*32
    const int wn = wid >> 2;       // n block: cols wn*64

    const int NK = K >> 6;

    // tile loader: 3 tiles (A0,B0,B1) of 128 rows x 128B each, SW128
    auto load_chunk = [&](int s) {
        const int kt = s << 6;
        const uint32_t sb = sbase + (uint32_t)(s & 1) * GSTAGE;
        const __half* pa0 = A0 + (size_t)row0 * K + kt;
        const __half* pb0 = B0 + (size_t)col0 * K + kt;
        const __half* pb1 = B1 + (size_t)col0 * K + kt;
        #pragma unroll
        for (int i = 0; i < 4; i++) {
            const int id = tid + i * 256;        // 0..1023
            const int r = id >> 3, c = id & 7;
            const uint32_t sw = SWZ(r * 128 + c * 16);
            const size_t go = (size_t)r * K + c * 8;
            cp16(sb + sw,           pa0 + go);
            cp16(sb + 16384u + sw,  pb0 + go);
            cp16(sb + 32768u + sw,  pb1 + go);
        }
        asm volatile("cp.async.commit_group;" ::: "memory");
    };

    float acc[16][4];              // [mt*8 + nt][4]
    #pragma unroll
    for (int i = 0; i < 16; i++)
        #pragma unroll
        for (int j = 0; j < 4; j++) acc[i][j] = 0.f;

    load_chunk(0);
    if (NK > 1) load_chunk(1);

    const int arow[2] = { wm * 32 + (lid & 15),
                          wm * 32 + 16 + (lid & 15) };
    const int ahalf = lid >> 4;
    const int brow_base = wn * 64 + ((lid >> 4) << 3) + (lid & 7);
    const int bhalf = (lid >> 3) & 1;

    for (int s = 0; s < NK; s++) {
        if (s + 1 < NK) asm volatile("cp.async.wait_group 1;" ::: "memory");
        else            asm volatile("cp.async.wait_group 0;" ::: "memory");
        __syncthreads();

        const uint32_t sb  = sbase + (uint32_t)(s & 1) * GSTAGE;
        const uint32_t SA0 = sb;
        const uint32_t SBT[2] = { sb + 16384u, sb + 32768u };

        #pragma unroll
        for (int ks = 0; ks < 4; ks++) {
            uint32_t ah[2][4];
            #pragma unroll
            for (int mt = 0; mt < 2; mt++) {
                const int r = arow[mt];
                const uint32_t off = (uint32_t)r * 128u
                                   + (uint32_t)(((2 * ks + ahalf) ^ (r & 7)) * 16);
                ldm4(SA0 + off, ah[mt]);
            }
            #pragma unroll
            for (int pass = 0; pass < 2; pass++) {
                const uint32_t SB = SBT[pass];
                #pragma unroll
                for (int ng = 0; ng < 4; ng++) {
                    const int r = brow_base + ng * 16;
                    const uint32_t off = (uint32_t)r * 128u
                                       + (uint32_t)(((2 * ks + bhalf) ^ (r & 7)) * 16);
                    uint32_t t[4];
                    ldm4(SB + off, t);
                    #pragma unroll
                    for (int mt = 0; mt < 2; mt++) {
                        mma16816(acc[mt * 8 + 2 * ng],     ah[mt], t);
                        mma16816(acc[mt * 8 + 2 * ng + 1], ah[mt], t + 2);
                    }
                }
            }
        }
        if (s + 2 < NK) {
            __syncthreads();         // all warps done reading buf s
            load_chunk(s + 2);       // overwrite it with chunk s+2
        }
    }

    // epilogue: write accumulators (+bias)
    #pragma unroll
    for (int mt = 0; mt < 2; mt++) {
        #pragma unroll
        for (int nt = 0; nt < 8; nt++) {
            const float* c = acc[mt * 8 + nt];
            const int r0 = row0 + wm * 32 + mt * 16 + (lid >> 2);
            const int cc = col0 + wn * 64 + nt * 8 + (lid & 3) * 2;
            float b0v = 0.f, b1v = 0.f;
            if (bias) { b0v = bias[cc]; b1v = bias[cc + 1]; }
            *(float2*)&C[(size_t)r0 * N + cc] =
                make_float2(c[0] + b0v, c[1] + b1v);
            *(float2*)&C[(size_t)(r0 + 8) * N + cc] =
                make_float2(c[2] + b0v, c[3] + b1v);
        }
    }
}

// ------------------------- fp32 -> fp16 convert ------------------------------
__global__ void __launch_bounds__(256) half_kernel(
    const float* __restrict__ in, __half* __restrict__ h, int n4)
{
    int i = blockIdx.x * blockDim.x + threadIdx.x;
    if (i >= n4) return;
    float4 v = ((const float4*)in)[i];
    __half2 a = __floats2half2_rn(v.x, v.y);
    __half2 b = __floats2half2_rn(v.z, v.w);
    *(__half2*)&h[(size_t)i * 4]     = a;
    *(__half2*)&h[(size_t)i * 4 + 2] = b;
}

// -------------------- transpose + fp16 hi/lo split: W[K,N] -> T0/T1 [N,K] ----
__global__ void __launch_bounds__(256) tsplit_kernel(
    const float* __restrict__ W, __half* __restrict__ T0,
    __half* __restrict__ T1, int K, int N)
{
    __shared__ float t[32][33];
    const int n0 = blockIdx.x * 32, k0 = blockIdx.y * 32;
    const int x = threadIdx.x & 31, y = threadIdx.x >> 5;   // 32 x 8
    #pragma unroll
    for (int j = 0; j < 32; j += 8)
        t[y + j][x] = W[(size_t)(k0 + y + j) * N + n0 + x];
    __syncthreads();
    #pragma unroll
    for (int j = 0; j < 32; j += 8) {
        float v = t[x][y + j];
        __half hi = __float2half_rn(v);
        __half lo = __float2half_rn(v - __half2float(hi));
        size_t o = (size_t)(n0 + y + j) * K + k0 + x;
        T0[o] = hi; T1[o] = lo;
    }
}

// ------------------------- bucket sums: sx = [sum_q, sum_k] ------------------
__global__ void __launch_bounds__(256) bucket_sum_kernel(
    const float* __restrict__ qkv, float* __restrict__ sx)
{
    const int blk = blockIdx.x;              // bh*64 + u
    const int bh = blk >> 6, u = blk & 63;
    const int bi = bh >> 3, hi = bh & 7;
    const int e = threadIdx.x;               // 0..255
    const int col = (e < 128) ? (hi * DH + e) : (DMODEL + hi * DH + (e - 128));
    const float* base = qkv + ((size_t)(bi * TLEN + u * BSZ)) * QKVC + col;
    float a = 0.f;
    #pragma unroll 8
    for (int i = 0; i < BSZ; i++) a += base[(size_t)i * QKVC];
    sx[(size_t)blk * 256 + e] = a;
}

// ---------------- SortNet + Gumbel-Sinkhorn + top-1 --------------------------
__global__ void __launch_bounds__(256) sortnet_sinkhorn_kernel(
    const float* __restrict__ sx, const float* __restrict__ sw,
    const float* __restrict__ gum, int* __restrict__ idx_out,
    float* __restrict__ val_out)
{
    __shared__ float r[64][65];
    const int bh  = blockIdx.x;
    const int hi  = bh & 7;
    const int tid = threadIdx.x;
    const int u   = tid >> 2;                // 0..63
    const int vq  = (tid & 3) * 16;          // 0,16,32,48

    float acc[16];
    #pragma unroll
    for (int v = 0; v < 16; v++) acc[v] = 0.f;
    const float* sxrow = sx + ((size_t)(bh * 64 + u)) * 256;
    const float* W = sw + (size_t)hi * 256 * 64 + vq;
    for (int e = 0; e < 256; e++) {
        float s = sxrow[e];
        #pragma unroll
        for (int v = 0; v < 16; v++) acc[v] += s * W[(size_t)e * 64 + v];
    }
    #pragma unroll
    for (int v = 0; v < 16; v++) {
        float R = acc[v];
        R = (R > 0.f) ? R : 0.01f * R;
        float gu = gum[((size_t)(bh * 64 + u)) * 64 + vq + v];
        float g  = -logf(-logf(gu + EPS_) + EPS_);
        r[u][vq + v] = (logf(fmaxf(R + EPS_, EPS_)) + g) / TEMP_;
    }
    __syncthreads();

    for (int it = 0; it < 5; it++) {
        if (tid < 64) {
            float m = -1e30f;
            for (int v = 0; v < 64; v++) m = fmaxf(m, r[tid][v]);
            float s = 0.f;
            for (int v = 0; v < 64; v++) s += __expf(r[tid][v] - m);
            float lse = m + logf(s);
            for (int v = 0; v < 64; v++) r[tid][v] -= lse;
        }
        __syncthreads();
        if (tid < 64) {
            float m = -1e30f;
            for (int i = 0; i < 64; i++) m = fmaxf(m, r[i][tid]);
            float s = 0.f;
            for (int i = 0; i < 64; i++) s += __expf(r[i][tid] - m);
            float lse = m + logf(s);
            for (int i = 0; i < 64; i++) r[i][tid] -= lse;
        }
        __syncthreads();
    }

    if (tid < 64) {
        int best = 0; float bm = r[tid][0];
        for (int v = 1; v < 64; v++) {
            float rv = r[tid][v];
            if (rv > bm) { bm = rv; best = v; }
        }
        idx_out[bh * 64 + tid] = best;
        val_out[bh * 64 + tid] = __expf(bm);
    }
}

// ------------------------- bucketed attention --------------------------------
#define ATT_SMEM_FLOATS ((64 + 128) * 132)
#define ATT_SMEM_BYTES  (ATT_SMEM_FLOATS * 4)

__global__ void __launch_bounds__(256, 2) attn_kernel(
    const float* __restrict__ qkv, const int* __restrict__ idxv,
    const float* __restrict__ valv, __half* __restrict__ ao0)
{
    extern __shared__ float sm[];
    float* qs = sm;               // 64 x 132 : q, then P (reused)
    float* kv = sm + 64 * 132;    // 128 x 132 : k2, then v2 (reused)

    const int blk = blockIdx.x;
    const int bh = blk >> 6, u = blk & 63;
    const int bi = bh >> 3, hi = bh & 7;
    const int tid = threadIdx.x;
    const int tx = tid & 31, ty = tid >> 5;

    const int   src = idxv[blk];
    const float pv  = valv[blk];

    const size_t rowq = (size_t)(bi * TLEN + u * BSZ);
    const size_t rows = (size_t)(bi * TLEN + src * BSZ);
    const int colq = hi * DH;

    for (int n = tid; n < 64 * 128; n += 256) {
        int i = n >> 7, dd = n & 127;
        qs[i * 132 + dd] = qkv[(rowq + i) * QKVC + colq + dd];
    }
    for (int n = tid; n < 128 * 128; n += 256) {
        int j = n >> 7, dd = n & 127;
        float xv;
        if (j < 64) xv = pv * qkv[(rows + j) * QKVC + DMODEL + colq + dd];
        else        xv =      qkv[(rowq + j - 64) * QKVC + DMODEL + colq + dd];
        kv[j * 132 + dd] = xv;
    }
    __syncthreads();

    float acc[8][4];
    #pragma unroll
    for (int a = 0; a < 8; a++)
        #pragma unroll
        for (int b = 0; b < 4; b++) acc[a][b] = 0.f;

    for (int dd = 0; dd < 128; dd += 4) {
        float4 bq[4];
        #pragma unroll
        for (int jj = 0; jj < 4; jj++)
            bq[jj] = *(const float4*)&kv[(tx + 32 * jj) * 132 + dd];
        #pragma unroll
        for (int ii = 0; ii < 8; ii++) {
            float4 aq = *(const float4*)&qs[(ty + 8 * ii) * 132 + dd];
            #pragma unroll
            for (int jj = 0; jj < 4; jj++)
                acc[ii][jj] += aq.x * bq[jj].x + aq.y * bq[jj].y
                             + aq.z * bq[jj].z + aq.w * bq[jj].w;
        }
    }

    float p[8][4];
    #pragma unroll
    for (int ii = 0; ii < 8; ii++) {
        float m = -1e30f;
        #pragma unroll
        for (int jj = 0; jj < 4; jj++) {
            acc[ii][jj] *= SCALE_;
            m = fmaxf(m, acc[ii][jj]);
        }
        #pragma unroll
        for (int off = 16; off > 0; off >>= 1)
            m = fmaxf(m, __shfl_xor_sync(0xffffffffu, m, off));
        float s = 0.f;
        #pragma unroll
        for (int jj = 0; jj < 4; jj++) {
            p[ii][jj] = __expf(acc[ii][jj] - m);
            s += p[ii][jj];
        }
        #pragma unroll
        for (int off = 16; off > 0; off >>= 1)
            s += __shfl_xor_sync(0xffffffffu, s, off);
        float inv = 1.f / s;
        #pragma unroll
        for (int jj = 0; jj < 4; jj++) p[ii][jj] *= inv;
    }
    __syncthreads();

    #pragma unroll
    for (int ii = 0; ii < 8; ii++)
        #pragma unroll
        for (int jj = 0; jj < 4; jj++)
            qs[(ty + 8 * ii) * 132 + tx + 32 * jj] = p[ii][jj];

    for (int n = tid; n < 128 * 128; n += 256) {
        int j = n >> 7, dd = n & 127;
        float xv;
        if (j < 64) xv = pv * qkv[(rows + j) * QKVC + 2 * DMODEL + colq + dd];
        else        xv =      qkv[(rowq + j - 64) * QKVC + 2 * DMODEL + colq + dd];
        kv[j * 132 + dd] = xv;
    }
    __syncthreads();

    float acc2[8][4];
    #pragma unroll
    for (int a = 0; a < 8; a++)
        #pragma unroll
        for (int b = 0; b < 4; b++) acc2[a][b] = 0.f;

    for (int j = 0; j < 128; j += 4) {
        float bvv[4][4];
        #pragma unroll
        for (int jx = 0; jx < 4; jx++)
            #pragma unroll
            for (int ee = 0; ee < 4; ee++)
                bvv[jx][ee] = kv[(j + jx) * 132 + tx + 32 * ee];
        #pragma unroll
        for (int ii = 0; ii < 8; ii++) {
            float4 av = *(const float4*)&qs[(ty + 8 * ii) * 132 + j];
            #pragma unroll
            for (int ee = 0; ee < 4; ee++)
                acc2[ii][ee] += av.x * bvv[0][ee] + av.y * bvv[1][ee]
                              + av.z * bvv[2][ee] + av.w * bvv[3][ee];
        }
    }

    #pragma unroll
    for (int ii = 0; ii < 8; ii++) {
        const size_t row = rowq + (ty + 8 * ii);
        #pragma unroll
        for (int ee = 0; ee < 4; ee++) {
            size_t o = row * DMODEL + colq + tx + 32 * ee;
            ao0[o] = __float2half_rn(acc2[ii][ee]);
        }
    }
}

// ------------------------- launcher ------------------------------------------
extern "C" void kernel_launch(void* const* d_in, const int* in_sizes, int n_in,
                              void* d_out, int out_size)
{
    const float* x      = (const float*)d_in[0];
    const float* gumbel = (const float*)d_in[1];
    const float* w_qkv  = (const float*)d_in[2];
    const float* sort_w = (const float*)d_in[3];
    const float* w_out  = (const float*)d_in[4];
    const float* b_out  = (const float*)d_in[5];
    float* out = (float*)d_out;

    float *qkv, *sx, *val; int* idx;
    __half *x0, *wq0, *wq1, *wo0, *wo1, *ao0;
    cudaGetSymbolAddress((void**)&qkv, g_qkv);
    cudaGetSymbolAddress((void**)&sx,  g_sx);
    cudaGetSymbolAddress((void**)&idx, g_idx);
    cudaGetSymbolAddress((void**)&val, g_val);
    cudaGetSymbolAddress((void**)&x0,  g_x0);
    cudaGetSymbolAddress((void**)&wq0, g_wq0);
    cudaGetSymbolAddress((void**)&wq1, g_wq1);
    cudaGetSymbolAddress((void**)&wo0, g_wo0);
    cudaGetSymbolAddress((void**)&wo1, g_wo1);
    cudaGetSymbolAddress((void**)&ao0, g_ao0);

    cudaFuncSetAttribute(gemm_mma,
                         cudaFuncAttributeMaxDynamicSharedMemorySize, GEMM_SMEM);
    cudaFuncSetAttribute(attn_kernel,
                         cudaFuncAttributeMaxDynamicSharedMemorySize, ATT_SMEM_BYTES);

    // 0) convert/split inputs to fp16
    {
        int n4 = NROWS * DMODEL / 4;
        half_kernel<<<(n4 + 255) / 256, 256>>>(x, x0, n4);
    }
    tsplit_kernel<<<dim3(QKVC / 32, DMODEL / 32), 256>>>(w_qkv, wq0, wq1, DMODEL, QKVC);
    tsplit_kernel<<<dim3(DMODEL / 32, DMODEL / 32), 256>>>(w_out, wo0, wo1, DMODEL, DMODEL);

    // 1) qkv = x @ w_qkv  (HMMA fp16 2-term)
    gemm_mma<<<dim3(QKVC / 128, NROWS / 128), 256, GEMM_SMEM>>>(
        x0, wq0, wq1, nullptr, qkv, NROWS, QKVC, DMODEL);

    // 2) bucket sums
    bucket_sum_kernel<<<BH * NBUCK, 256>>>(qkv, sx);

    // 3) SortNet + gumbel-sinkhorn + top-1
    sortnet_sinkhorn_kernel<<<BH, 256>>>(sx, sort_w, gumbel, idx, val);

    // 4) bucketed attention (fused top-1 gather; writes fp16)
    attn_kernel<<<BH * NBUCK, 256, ATT_SMEM_BYTES>>>(qkv, idx, val, ao0);

    // 5) out = ao @ w_out + b_out  (HMMA fp16 2-term)
    gemm_mma<<<dim3(DMODEL / 128, NROWS / 128), 256, GEMM_SMEM>>>(
        ao0, wo0, wo1, b_out, out, NROWS, DMODEL, DMODEL);
}

// round 13
// speedup vs baseline: 3.5508x; 1.2947x over previous
#include <cuda_runtime.h>
#include <cuda_bf16.h>
#include <cuda_fp16.h>
#include <math.h>
#include <stdint.h>

#define HEADS   8
#define NBUCK   64
#define BSZ     64
#define DH      128
#define DMODEL  1024
#define TLEN    4096
#define NB      2
#define BH      16          // NB*HEADS
#define NROWS   8192        // NB*TLEN
#define QKVC    3072
#define TEMP_   0.75f
#define EPS_    1e-6f
#define SCALE_  0.03125f    // 1024^-0.5

// ------------------------- device scratch (no allocs allowed) ----------------
__device__ float   g_qkv[(size_t)NROWS * QKVC];     // fp32 qkv, ~100.7MB
__device__ float   g_sx[BH * NBUCK * 256];
__device__ int     g_idx[BH * NBUCK];
__device__ float   g_val[BH * NBUCK];
__device__ __half  g_x0[(size_t)NROWS * DMODEL];    // x in fp16
__device__ __half  g_wq0[(size_t)QKVC * DMODEL];    // w_qkv^T hi
__device__ __half  g_wq1[(size_t)QKVC * DMODEL];    // w_qkv^T lo
__device__ __half  g_wo0[(size_t)DMODEL * DMODEL];  // w_out^T hi
__device__ __half  g_wo1[(size_t)DMODEL * DMODEL];  // w_out^T lo
__device__ __half  g_ao0[(size_t)NROWS * DMODEL];   // attn out fp16

// ------------------------- helpers -------------------------------------------
#define SWZ(o) ((uint32_t)(o) ^ ((((uint32_t)(o)) >> 3) & 0x70u))

__device__ __forceinline__ uint32_t s2u(const void* p) {
    uint32_t a;
    asm("{ .reg .u64 t; cvta.to.shared.u64 t, %1; cvt.u32.u64 %0, t; }" : "=r"(a) : "l"(p));
    return a;
}

__device__ __forceinline__ void cp16(uint32_t s, const void* g) {
    asm volatile("cp.async.cg.shared.global [%0], [%1], 16;\n" :: "r"(s), "l"(g));
}

__device__ __forceinline__ void ldm4(uint32_t addr, uint32_t* r) {
    asm volatile("ldmatrix.sync.aligned.m8n8.x4.shared.b16 {%0,%1,%2,%3}, [%4];"
                 : "=r"(r[0]), "=r"(r[1]), "=r"(r[2]), "=r"(r[3]) : "r"(addr));
}

__device__ __forceinline__ void ldm4t(uint32_t addr, uint32_t* r) {
    asm volatile("ldmatrix.sync.aligned.m8n8.x4.trans.shared.b16 {%0,%1,%2,%3}, [%4];"
                 : "=r"(r[0]), "=r"(r[1]), "=r"(r[2]), "=r"(r[3]) : "r"(addr));
}

__device__ __forceinline__ void mma16816(float* c, const uint32_t* a, const uint32_t* b) {
    asm volatile(
        "mma.sync.aligned.m16n8k16.row.col.f32.f16.f16.f32 "
        "{%0,%1,%2,%3}, {%4,%5,%6,%7}, {%8,%9}, {%0,%1,%2,%3};"
        : "+f"(c[0]), "+f"(c[1]), "+f"(c[2]), "+f"(c[3])
        : "r"(a[0]), "r"(a[1]), "r"(a[2]), "r"(a[3]), "r"(b[0]), "r"(b[1]));
}

// ------------------------- fp16 2-term HMMA GEMM -----------------------------
#define GSTAGE 49152
#define GEMM_SMEM (2 * GSTAGE)

__global__ void __launch_bounds__(256, 2) gemm_mma(
    const __half* __restrict__ A0,
    const __half* __restrict__ B0, const __half* __restrict__ B1,
    const float* __restrict__ bias, float* __restrict__ C,
    int M, int N, int K)
{
    extern __shared__ char smem[];
    const uint32_t sbase = s2u(smem);

    const int tid = threadIdx.x, wid = tid >> 5, lid = tid & 31;
    const int col0 = blockIdx.x * 128, row0 = blockIdx.y * 128;
    const int wm = wid & 3;
    const int wn = wid >> 2;

    const int NK = K >> 6;

    auto load_chunk = [&](int s) {
        const int kt = s << 6;
        const uint32_t sb = sbase + (uint32_t)(s & 1) * GSTAGE;
        const __half* pa0 = A0 + (size_t)row0 * K + kt;
        const __half* pb0 = B0 + (size_t)col0 * K + kt;
        const __half* pb1 = B1 + (size_t)col0 * K + kt;
        #pragma unroll
        for (int i = 0; i < 4; i++) {
            const int id = tid + i * 256;
            const int r = id >> 3, c = id & 7;
            const uint32_t sw = SWZ(r * 128 + c * 16);
            const size_t go = (size_t)r * K + c * 8;
            cp16(sb + sw,           pa0 + go);
            cp16(sb + 16384u + sw,  pb0 + go);
            cp16(sb + 32768u + sw,  pb1 + go);
        }
        asm volatile("cp.async.commit_group;" ::: "memory");
    };

    float acc[16][4];
    #pragma unroll
    for (int i = 0; i < 16; i++)
        #pragma unroll
        for (int j = 0; j < 4; j++) acc[i][j] = 0.f;

    load_chunk(0);
    if (NK > 1) load_chunk(1);

    const int arow[2] = { wm * 32 + (lid & 15),
                          wm * 32 + 16 + (lid & 15) };
    const int ahalf = lid >> 4;
    const int brow_base = wn * 64 + ((lid >> 4) << 3) + (lid & 7);
    const int bhalf = (lid >> 3) & 1;

    for (int s = 0; s < NK; s++) {
        if (s + 1 < NK) asm volatile("cp.async.wait_group 1;" ::: "memory");
        else            asm volatile("cp.async.wait_group 0;" ::: "memory");
        __syncthreads();

        const uint32_t sb  = sbase + (uint32_t)(s & 1) * GSTAGE;
        const uint32_t SA0 = sb;
        const uint32_t SBT[2] = { sb + 16384u, sb + 32768u };

        #pragma unroll
        for (int ks = 0; ks < 4; ks++) {
            uint32_t ah[2][4];
            #pragma unroll
            for (int mt = 0; mt < 2; mt++) {
                const int r = arow[mt];
                const uint32_t off = (uint32_t)r * 128u
                                   + (uint32_t)(((2 * ks + ahalf) ^ (r & 7)) * 16);
                ldm4(SA0 + off, ah[mt]);
            }
            #pragma unroll
            for (int pass = 0; pass < 2; pass++) {
                const uint32_t SB = SBT[pass];
                #pragma unroll
                for (int ng = 0; ng < 4; ng++) {
                    const int r = brow_base + ng * 16;
                    const uint32_t off = (uint32_t)r * 128u
                                       + (uint32_t)(((2 * ks + bhalf) ^ (r & 7)) * 16);
                    uint32_t t[4];
                    ldm4(SB + off, t);
                    #pragma unroll
                    for (int mt = 0; mt < 2; mt++) {
                        mma16816(acc[mt * 8 + 2 * ng],     ah[mt], t);
                        mma16816(acc[mt * 8 + 2 * ng + 1], ah[mt], t + 2);
                    }
                }
            }
        }
        if (s + 2 < NK) {
            __syncthreads();
            load_chunk(s + 2);
        }
    }

    #pragma unroll
    for (int mt = 0; mt < 2; mt++) {
        #pragma unroll
        for (int nt = 0; nt < 8; nt++) {
            const float* c = acc[mt * 8 + nt];
            const int r0 = row0 + wm * 32 + mt * 16 + (lid >> 2);
            const int cc = col0 + wn * 64 + nt * 8 + (lid & 3) * 2;
            float b0v = 0.f, b1v = 0.f;
            if (bias) { b0v = bias[cc]; b1v = bias[cc + 1]; }
            *(float2*)&C[(size_t)r0 * N + cc] =
                make_float2(c[0] + b0v, c[1] + b1v);
            *(float2*)&C[(size_t)(r0 + 8) * N + cc] =
                make_float2(c[2] + b0v, c[3] + b1v);
        }
    }
}

// ------------------------- fp32 -> fp16 convert ------------------------------
__global__ void __launch_bounds__(256) half_kernel(
    const float* __restrict__ in, __half* __restrict__ h, int n4)
{
    int i = blockIdx.x * blockDim.x + threadIdx.x;
    if (i >= n4) return;
    float4 v = ((const float4*)in)[i];
    __half2 a = __floats2half2_rn(v.x, v.y);
    __half2 b = __floats2half2_rn(v.z, v.w);
    *(__half2*)&h[(size_t)i * 4]     = a;
    *(__half2*)&h[(size_t)i * 4 + 2] = b;
}

// -------------------- transpose + fp16 hi/lo split: W[K,N] -> T0/T1 [N,K] ----
__global__ void __launch_bounds__(256) tsplit_kernel(
    const float* __restrict__ W, __half* __restrict__ T0,
    __half* __restrict__ T1, int K, int N)
{
    __shared__ float t[32][33];
    const int n0 = blockIdx.x * 32, k0 = blockIdx.y * 32;
    const int x = threadIdx.x & 31, y = threadIdx.x >> 5;
    #pragma unroll
    for (int j = 0; j < 32; j += 8)
        t[y + j][x] = W[(size_t)(k0 + y + j) * N + n0 + x];
    __syncthreads();
    #pragma unroll
    for (int j = 0; j < 32; j += 8) {
        float v = t[x][y + j];
        __half hi = __float2half_rn(v);
        __half lo = __float2half_rn(v - __half2float(hi));
        size_t o = (size_t)(n0 + y + j) * K + k0 + x;
        T0[o] = hi; T1[o] = lo;
    }
}

// ------------------------- bucket sums: sx = [sum_q, sum_k] ------------------
__global__ void __launch_bounds__(256) bucket_sum_kernel(
    const float* __restrict__ qkv, float* __restrict__ sx)
{
    const int blk = blockIdx.x;
    const int bh = blk >> 6, u = blk & 63;
    const int bi = bh >> 3, hi = bh & 7;
    const int e = threadIdx.x;
    const int col = (e < 128) ? (hi * DH + e) : (DMODEL + hi * DH + (e - 128));
    const float* base = qkv + ((size_t)(bi * TLEN + u * BSZ)) * QKVC + col;
    float a = 0.f;
    #pragma unroll 8
    for (int i = 0; i < BSZ; i++) a += base[(size_t)i * QKVC];
    sx[(size_t)blk * 256 + e] = a;
}

// ---------------- SortNet + Gumbel-Sinkhorn + top-1 --------------------------
__global__ void __launch_bounds__(256) sortnet_sinkhorn_kernel(
    const float* __restrict__ sx, const float* __restrict__ sw,
    const float* __restrict__ gum, int* __restrict__ idx_out,
    float* __restrict__ val_out)
{
    __shared__ float r[64][65];
    const int bh  = blockIdx.x;
    const int hi  = bh & 7;
    const int tid = threadIdx.x;
    const int u   = tid >> 2;
    const int vq  = (tid & 3) * 16;

    float acc[16];
    #pragma unroll
    for (int v = 0; v < 16; v++) acc[v] = 0.f;
    const float* sxrow = sx + ((size_t)(bh * 64 + u)) * 256;
    const float* W = sw + (size_t)hi * 256 * 64 + vq;
    for (int e = 0; e < 256; e++) {
        float s = sxrow[e];
        #pragma unroll
        for (int v = 0; v < 16; v++) acc[v] += s * W[(size_t)e * 64 + v];
    }
    #pragma unroll
    for (int v = 0; v < 16; v++) {
        float R = acc[v];
        R = (R > 0.f) ? R : 0.01f * R;
        float gu = gum[((size_t)(bh * 64 + u)) * 64 + vq + v];
        float g  = -logf(-logf(gu + EPS_) + EPS_);
        r[u][vq + v] = (logf(fmaxf(R + EPS_, EPS_)) + g) / TEMP_;
    }
    __syncthreads();

    for (int it = 0; it < 5; it++) {
        if (tid < 64) {
            float m = -1e30f;
            for (int v = 0; v < 64; v++) m = fmaxf(m, r[tid][v]);
            float s = 0.f;
            for (int v = 0; v < 64; v++) s += __expf(r[tid][v] - m);
            float lse = m + logf(s);
            for (int v = 0; v < 64; v++) r[tid][v] -= lse;
        }
        __syncthreads();
        if (tid < 64) {
            float m = -1e30f;
            for (int i = 0; i < 64; i++) m = fmaxf(m, r[i][tid]);
            float s = 0.f;
            for (int i = 0; i < 64; i++) s += __expf(r[i][tid] - m);
            float lse = m + logf(s);
            for (int i = 0; i < 64; i++) r[i][tid] -= lse;
        }
        __syncthreads();
    }

    if (tid < 64) {
        int best = 0; float bm = r[tid][0];
        for (int v = 1; v < 64; v++) {
            float rv = r[tid][v];
            if (rv > bm) { bm = rv; best = v; }
        }
        idx_out[bh * 64 + tid] = best;
        val_out[bh * 64 + tid] = __expf(bm);
    }
}

// ------------------------- bucketed attention (HMMA) -------------------------
// One CTA per (bh, bucket). 8 warps: wm = wid&3 (16 rows each), wn = wid>>2
// (64-col half). QK: q fp16 x (k_hi + k_lo). PV: (p_hi+p_lo) x (v_hi+v_lo),
// term pl*vl dropped (~2^-22).
// smem overlay (96KB dynamic):
//   phase1: q [0,16K)          k_hi [16K,48K)  k_lo [48K,80K)
//   phase2: p_hi [0,16K) p_lo [16K,32K) v_hi [32K,64K) v_lo [64K,96K)
// All fp16 tiles: rows of 128B (64 cols), SW128 swizzle; "subtile" = col-half.
#define ATT_SMEM 98304
#define OFF_Q    0u
#define OFF_KH   16384u
#define OFF_KL   49152u
#define OFF_PH   0u
#define OFF_PL   16384u
#define OFF_VH   32768u
#define OFF_VL   65536u

__global__ void __launch_bounds__(256, 2) attn_kernel(
    const float* __restrict__ qkv, const int* __restrict__ idxv,
    const float* __restrict__ valv, __half* __restrict__ ao0)
{
    extern __shared__ char smem[];
    const uint32_t sbase = s2u(smem);
    __shared__ float redm[2][64], reds[2][64];

    const int blk = blockIdx.x;
    const int bh = blk >> 6, u = blk & 63;
    const int bi = bh >> 3, hi = bh & 7;
    const int tid = threadIdx.x, wid = tid >> 5, lid = tid & 31;
    const int wm = wid & 3, wn = wid >> 2;

    const int   src = idxv[blk];
    const float pv  = valv[blk];

    const size_t rowq = (size_t)(bi * TLEN + u * BSZ);
    const size_t rows = (size_t)(bi * TLEN + src * BSZ);
    const int colq = hi * DH;

    // ---- phase 1 loads: q (fp16), k2 (fp16 hi/lo, gathered+scaled) ----------
    #pragma unroll
    for (int it = 0; it < 16; it++) {          // q: 4096 half2
        const int h = tid + it * 256;
        const int i = h >> 6, dd = (h & 63) * 2;
        float2 v = *(const float2*)&qkv[(rowq + i) * QKVC + colq + dd];
        const uint32_t sub = (uint32_t)(dd >> 6);
        const uint32_t byte = (uint32_t)i * 128u + (uint32_t)(dd & 63) * 2u;
        *(__half2*)(smem + OFF_Q + sub * 8192u + SWZ(byte)) =
            __floats2half2_rn(v.x, v.y);
    }
    #pragma unroll
    for (int it = 0; it < 32; it++) {          // k2: 8192 half2 pairs
        const int h = tid + it * 256;
        const int j = h >> 6, dd = (h & 63) * 2;
        float2 v;
        if (j < 64) {
            v = *(const float2*)&qkv[(rows + j) * QKVC + DMODEL + colq + dd];
            v.x *= pv; v.y *= pv;
        } else {
            v = *(const float2*)&qkv[(rowq + j - 64) * QKVC + DMODEL + colq + dd];
        }
        __half h0 = __float2half_rn(v.x), h1 = __float2half_rn(v.y);
        __half l0 = __float2half_rn(v.x - __half2float(h0));
        __half l1 = __float2half_rn(v.y - __half2float(h1));
        const uint32_t sub = (uint32_t)(dd >> 6);
        const uint32_t swz = SWZ((uint32_t)j * 128u + (uint32_t)(dd & 63) * 2u);
        *(__half2*)(smem + OFF_KH + sub * 16384u + swz) = __halves2half2(h0, h1);
        *(__half2*)(smem + OFF_KL + sub * 16384u + swz) = __halves2half2(l0, l1);
    }
    __syncthreads();

    // ---- QK: acc[nt][4], rows wm*16+(lid>>2)(+8), cols wn*64+nt*8+(lid&3)*2 -
    float acc[8][4];
    #pragma unroll
    for (int a = 0; a < 8; a++)
        #pragma unroll
        for (int b = 0; b < 4; b++) acc[a][b] = 0.f;

    const int ar    = wm * 16 + (lid & 15);
    const int ahalf = lid >> 4;
    const int brow_base = wn * 64 + ((lid >> 4) << 3) + (lid & 7);
    const int bhalf = (lid >> 3) & 1;

    #pragma unroll
    for (int ks = 0; ks < 8; ks++) {
        const uint32_t sub = (uint32_t)(ks >> 2);
        const int ksl = ks & 3;
        uint32_t a4[4];
        {
            const uint32_t off = (uint32_t)ar * 128u
                               + (uint32_t)(((2 * ksl + ahalf) ^ (ar & 7)) * 16);
            ldm4(sbase + OFF_Q + sub * 8192u + off, a4);
        }
        #pragma unroll
        for (int pass = 0; pass < 2; pass++) {
            const uint32_t KB = (pass == 0 ? OFF_KH : OFF_KL) + sub * 16384u;
            #pragma unroll
            for (int ng = 0; ng < 4; ng++) {
                const int r = brow_base + ng * 16;
                const uint32_t off = (uint32_t)r * 128u
                                   + (uint32_t)(((2 * ksl + bhalf) ^ (r & 7)) * 16);
                uint32_t t[4];
                ldm4(sbase + KB + off, t);
                mma16816(acc[2 * ng],     a4, t);
                mma16816(acc[2 * ng + 1], a4, t + 2);
            }
        }
    }

    // ---- softmax over j (128) ------------------------------------------------
    const int r0 = wm * 16 + (lid >> 2);
    float m0 = -1e30f, m1 = -1e30f;
    #pragma unroll
    for (int nt = 0; nt < 8; nt++) {
        #pragma unroll
        for (int b = 0; b < 4; b++) acc[nt][b] *= SCALE_;
        m0 = fmaxf(m0, fmaxf(acc[nt][0], acc[nt][1]));
        m1 = fmaxf(m1, fmaxf(acc[nt][2], acc[nt][3]));
    }
    m0 = fmaxf(m0, __shfl_xor_sync(0xffffffffu, m0, 1));
    m0 = fmaxf(m0, __shfl_xor_sync(0xffffffffu, m0, 2));
    m1 = fmaxf(m1, __shfl_xor_sync(0xffffffffu, m1, 1));
    m1 = fmaxf(m1, __shfl_xor_sync(0xffffffffu, m1, 2));

    float s0 = 0.f, s1 = 0.f;
    #pragma unroll
    for (int nt = 0; nt < 8; nt++) {
        acc[nt][0] = __expf(acc[nt][0] - m0);
        acc[nt][1] = __expf(acc[nt][1] - m0);
        acc[nt][2] = __expf(acc[nt][2] - m1);
        acc[nt][3] = __expf(acc[nt][3] - m1);
        s0 += acc[nt][0] + acc[nt][1];
        s1 += acc[nt][2] + acc[nt][3];
    }
    s0 += __shfl_xor_sync(0xffffffffu, s0, 1);
    s0 += __shfl_xor_sync(0xffffffffu, s0, 2);
    s1 += __shfl_xor_sync(0xffffffffu, s1, 1);
    s1 += __shfl_xor_sync(0xffffffffu, s1, 2);

    if ((lid & 3) == 0) {
        redm[wn][r0] = m0;   reds[wn][r0] = s0;
        redm[wn][r0 + 8] = m1; reds[wn][r0 + 8] = s1;
    }
    __syncthreads();     // also guarantees: all warps past QK smem reads

    {
        const float mo0 = redm[wn ^ 1][r0],     so0 = reds[wn ^ 1][r0];
        const float mo1 = redm[wn ^ 1][r0 + 8], so1 = reds[wn ^ 1][r0 + 8];
        const float M0 = fmaxf(m0, mo0), M1 = fmaxf(m1, mo1);
        const float S0 = s0 * __expf(m0 - M0) + so0 * __expf(mo0 - M0);
        const float S1 = s1 * __expf(m1 - M1) + so1 * __expf(mo1 - M1);
        const float f0 = __expf(m0 - M0) / S0;
        const float f1 = __expf(m1 - M1) / S1;

        // p hi/lo -> smem (overwrites q / k_hi region)
        #pragma unroll
        for (int nt = 0; nt < 8; nt++) {
            const float p0 = acc[nt][0] * f0, p1 = acc[nt][1] * f0;
            const float p2 = acc[nt][2] * f1, p3 = acc[nt][3] * f1;
            const int j6 = nt * 8 + (lid & 3) * 2;     // col within 64-half
            __half h0 = __float2half_rn(p0), h1 = __float2half_rn(p1);
            __half h2 = __float2half_rn(p2), h3 = __float2half_rn(p3);
            const uint32_t sw0 = SWZ((uint32_t)r0 * 128u + (uint32_t)j6 * 2u);
            const uint32_t sw1 = SWZ((uint32_t)(r0 + 8) * 128u + (uint32_t)j6 * 2u);
            const uint32_t psub = (uint32_t)wn * 8192u;
            *(__half2*)(smem + OFF_PH + psub + sw0) = __halves2half2(h0, h1);
            *(__half2*)(smem + OFF_PH + psub + sw1) = __halves2half2(h2, h3);
            *(__half2*)(smem + OFF_PL + psub + sw0) = __halves2half2(
                __float2half_rn(p0 - __half2float(h0)),
                __float2half_rn(p1 - __half2float(h1)));
            *(__half2*)(smem + OFF_PL + psub + sw1) = __halves2half2(
                __float2half_rn(p2 - __half2float(h2)),
                __float2half_rn(p3 - __half2float(h3)));
        }
    }

    // ---- v2 load (fp16 hi/lo, gathered+scaled) — overwrites k region --------
    #pragma unroll
    for (int it = 0; it < 32; it++) {
        const int h = tid + it * 256;
        const int j = h >> 6, dd = (h & 63) * 2;
        float2 v;
        if (j < 64) {
            v = *(const float2*)&qkv[(rows + j) * QKVC + 2 * DMODEL + colq + dd];
            v.x *= pv; v.y *= pv;
        } else {
            v = *(const float2*)&qkv[(rowq + j - 64) * QKVC + 2 * DMODEL + colq + dd];
        }
        __half h0 = __float2half_rn(v.x), h1 = __float2half_rn(v.y);
        __half l0 = __float2half_rn(v.x - __half2float(h0));
        __half l1 = __float2half_rn(v.y - __half2float(h1));
        const uint32_t sub = (uint32_t)(dd >> 6);
        const uint32_t swz = SWZ((uint32_t)j * 128u + (uint32_t)(dd & 63) * 2u);
        *(__half2*)(smem + OFF_VH + sub * 16384u + swz) = __halves2half2(h0, h1);
        *(__half2*)(smem + OFF_VL + sub * 16384u + swz) = __halves2half2(l0, l1);
    }
    __syncthreads();

    // ---- PV: out[i][e] = sum_j p[i][j] v[j][e] ------------------------------
    #pragma unroll
    for (int a = 0; a < 8; a++)
        #pragma unroll
        for (int b = 0; b < 4; b++) acc[a][b] = 0.f;

    // trans-B lane mapping for v stored [j][e]
    const int vj_off = (lid & 7) + (((lid >> 3) & 1) << 3);  // row within k16
    const int veseg  = (lid >> 4) << 3;                      // +0 / +8 cols

    #pragma unroll
    for (int ks = 0; ks < 8; ks++) {
        const uint32_t psub = (uint32_t)(ks >> 2) * 8192u;   // p subtile (j-half)
        const int ksl = ks & 3;
        uint32_t aph[4], apl[4];
        {
            const uint32_t off = (uint32_t)ar * 128u
                               + (uint32_t)(((2 * ksl + ahalf) ^ (ar & 7)) * 16);
            ldm4(sbase + OFF_PH + psub + off, aph);
            ldm4(sbase + OFF_PL + psub + off, apl);
        }
        const int vj = ks * 16 + vj_off;
        #pragma unroll
        for (int ng = 0; ng < 4; ng++) {
            const int e6 = ng * 16 + veseg;                  // col within 64-half
            const uint32_t off = (uint32_t)vj * 128u
                               + (uint32_t)((((e6 >> 3) & 7) ^ (vj & 7)) * 16);
            const uint32_t vsub = (uint32_t)wn * 16384u;
            uint32_t th[4], tl[4];
            ldm4t(sbase + OFF_VH + vsub + off, th);
            ldm4t(sbase + OFF_VL + vsub + off, tl);
            // ph*vh + ph*vl + pl*vh
            mma16816(acc[2 * ng],     aph, th);
            mma16816(acc[2 * ng + 1], aph, th + 2);
            mma16816(acc[2 * ng],     aph, tl);
            mma16816(acc[2 * ng + 1], aph, tl + 2);
            mma16816(acc[2 * ng],     apl, th);
            mma16816(acc[2 * ng + 1], apl, th + 2);
        }
    }

    // ---- epilogue: fp16 out -------------------------------------------------
    #pragma unroll
    for (int nt = 0; nt < 8; nt++) {
        const int e = wn * 64 + nt * 8 + (lid & 3) * 2;
        const size_t o0 = (rowq + r0) * DMODEL + colq + e;
        const size_t o1 = (rowq + r0 + 8) * DMODEL + colq + e;
        *(__half2*)&ao0[o0] = __floats2half2_rn(acc[nt][0], acc[nt][1]);
        *(__half2*)&ao0[o1] = __floats2half2_rn(acc[nt][2], acc[nt][3]);
    }
}

// ------------------------- launcher ------------------------------------------
extern "C" void kernel_launch(void* const* d_in, const int* in_sizes, int n_in,
                              void* d_out, int out_size)
{
    const float* x      = (const float*)d_in[0];
    const float* gumbel = (const float*)d_in[1];
    const float* w_qkv  = (const float*)d_in[2];
    const float* sort_w = (const float*)d_in[3];
    const float* w_out  = (const float*)d_in[4];
    const float* b_out  = (const float*)d_in[5];
    float* out = (float*)d_out;

    float *qkv, *sx, *val; int* idx;
    __half *x0, *wq0, *wq1, *wo0, *wo1, *ao0;
    cudaGetSymbolAddress((void**)&qkv, g_qkv);
    cudaGetSymbolAddress((void**)&sx,  g_sx);
    cudaGetSymbolAddress((void**)&idx, g_idx);
    cudaGetSymbolAddress((void**)&val, g_val);
    cudaGetSymbolAddress((void**)&x0,  g_x0);
    cudaGetSymbolAddress((void**)&wq0, g_wq0);
    cudaGetSymbolAddress((void**)&wq1, g_wq1);
    cudaGetSymbolAddress((void**)&wo0, g_wo0);
    cudaGetSymbolAddress((void**)&wo1, g_wo1);
    cudaGetSymbolAddress((void**)&ao0, g_ao0);

    cudaFuncSetAttribute(gemm_mma,
                         cudaFuncAttributeMaxDynamicSharedMemorySize, GEMM_SMEM);
    cudaFuncSetAttribute(attn_kernel,
                         cudaFuncAttributeMaxDynamicSharedMemorySize, ATT_SMEM);

    // 0) convert/split inputs to fp16
    {
        int n4 = NROWS * DMODEL / 4;
        half_kernel<<<(n4 + 255) / 256, 256>>>(x, x0, n4);
    }
    tsplit_kernel<<<dim3(QKVC / 32, DMODEL / 32), 256>>>(w_qkv, wq0, wq1, DMODEL, QKVC);
    tsplit_kernel<<<dim3(DMODEL / 32, DMODEL / 32), 256>>>(w_out, wo0, wo1, DMODEL, DMODEL);

    // 1) qkv = x @ w_qkv  (HMMA fp16 2-term)
    gemm_mma<<<dim3(QKVC / 128, NROWS / 128), 256, GEMM_SMEM>>>(
        x0, wq0, wq1, nullptr, qkv, NROWS, QKVC, DMODEL);

    // 2) bucket sums
    bucket_sum_kernel<<<BH * NBUCK, 256>>>(qkv, sx);

    // 3) SortNet + gumbel-sinkhorn + top-1
    sortnet_sinkhorn_kernel<<<BH, 256>>>(sx, sort_w, gumbel, idx, val);

    // 4) bucketed attention (HMMA, fused top-1 gather; writes fp16)
    attn_kernel<<<BH * NBUCK, 256, ATT_SMEM>>>(qkv, idx, val, ao0);

    // 5) out = ao @ w_out + b_out  (HMMA fp16 2-term)
    gemm_mma<<<dim3(DMODEL / 128, NROWS / 128), 256, GEMM_SMEM>>>(
        ao0, wo0, wo1, b_out, out, NROWS, DMODEL, DMODEL);
}